// round 13
// baseline (speedup 1.0000x reference)
#include <cuda_runtime.h>
#include <cstdint>

#define OUT_ELE (16 * 256 * 256)

typedef unsigned long long u64;

#define PACK2(d, lo, hi) \
    asm("mov.b64 %0, {%1, %2};" : "=l"(d) : "r"(__float_as_uint(lo)), "r"(__float_as_uint(hi)))
#define UNPACK2(lo, hi, s) do { unsigned _ulo, _uhi; \
    asm("mov.b64 {%0, %1}, %2;" : "=r"(_ulo), "=r"(_uhi) : "l"(s)); \
    lo = __uint_as_float(_ulo); hi = __uint_as_float(_uhi); } while (0)
#define FMA2(d, a, b, c) \
    asm("fma.rn.f32x2 %0, %1, %2, %3;" : "=l"(d) : "l"(a), "l"(b), "l"(c))

// scratch
__device__ float g_pooled[16 * 256 * 64];           // 1 MB
__device__ float g_kv[131072 * 128];                // v lives in cols 64-127
__device__ u64   g_kd[131072 * 64];                 // 64 MB: dup-pair k (k_j,k_j)
__device__ float g_wt[4 * 64 * 129];                // per-chunk weight smem images
__device__ u64   g_qp[64 * 129];                    // packed-q smem image

// ---------------------------------------------------------------------------
// K0: pack weights + q into exact smem-image layouts (one launch, ~4us).
// ---------------------------------------------------------------------------
__global__ void __launch_bounds__(256) k_pack(
    const float* __restrict__ q,
    const float* __restrict__ wks,
    const float* __restrict__ wvs)
{
    const int i = blockIdx.x * 256 + threadIdx.x;
    if (i < 4 * 64 * 129) {
        const int chunk = i / 8256, rem = i % 8256, d = rem / 129, c = rem % 129;
        float val = 0.f;
        if (c < 128)
            val = (c < 64) ? wks[c * 256 + chunk * 64 + d]
                           : wvs[(c - 64) * 256 + chunk * 64 + d];
        g_wt[i] = val;
    }
    if (i < 64 * 129) {
        const int j = i / 129, rr = i % 129;
        u64 val = 0ull;
        if (rr < 128) PACK2(val, q[rr * 64 + j], q[(rr + 128) * 64 + j]);
        g_qp[i] = val;
    }
}

// ---------------------------------------------------------------------------
// K1: kv projection GEMM (+ pooled zeroing folded into first 256 blocks).
// Main loop identical to the measured 204us version. Epilogue now writes
// k as duplicated pairs into g_kd (consumed mov-free by k_attn) and v into
// g_kv cols 64-127 (k no longer stored there).
// ---------------------------------------------------------------------------
#define SP_F  (64 * 130)
#define SW_RS 129
#define SMEM_PROJ ((SP_F + 64 * SW_RS) * 4)

__global__ void __launch_bounds__(256, 2) k_proj(
    const float* __restrict__ x)
{
    extern __shared__ float sm[];
    float* sp_f = sm;                 // [64][130] f32 == [64][65] u64
    u64*   sp64 = (u64*)sp_f;
    float* sw   = sm + SP_F;          // [64][129]  (16B-aligned)

    const int tid  = threadIdx.x;
    const int lane = tid & 31;
    const int w    = tid >> 5;
    const int tbase = blockIdx.x * 128;

    // folded pooled zeroing
    if (blockIdx.x < 256) {
        reinterpret_cast<float4*>(g_pooled)[blockIdx.x * 256 + tid] =
            make_float4(0.f, 0.f, 0.f, 0.f);
    }

    u64 acc[8][4];
    #pragma unroll
    for (int tp = 0; tp < 8; tp++)
        #pragma unroll
        for (int c = 0; c < 4; c++) acc[tp][c] = 0ull;

    for (int chunk = 0; chunk < 4; chunk++) {
        const int d0 = chunk * 64;

        // fill sw: linear float4 copy of the image (coalesced, conflict-free)
        {
            const float4* wsrc = (const float4*)(g_wt + chunk * 8256);
            float4* wdst = (float4*)sw;
            #pragma unroll
            for (int it = 0; it < 9; it++) {
                const int i = it * 256 + tid;
                if (i < 2064) wdst[i] = wsrc[i];
            }
        }
        // fill sp: pair-packed x (STS 2-way max)
        #pragma unroll
        for (int rr = 0; rr < 16; rr++) {
            const int tl = w * 16 + rr;
            const float* xp = x + (size_t)(tbase + tl) * 256 + d0;
            const int g = tl >> 1, h = tl & 1;
            sp_f[lane * 130 + g * 2 + h]        = xp[lane];
            sp_f[(32 + lane) * 130 + g * 2 + h] = xp[32 + lane];
        }
        __syncthreads();

        #pragma unroll 2
        for (int d = 0; d < 64; d++) {
            u64 xq[8];
            #pragma unroll
            for (int tp = 0; tp < 8; tp++)
                xq[tp] = sp64[d * 65 + w * 8 + tp];          // broadcast LDS.64
            const float w0 = sw[d * SW_RS +       lane];
            const float w1 = sw[d * SW_RS +  32 + lane];
            const float w2 = sw[d * SW_RS +  64 + lane];
            const float w3 = sw[d * SW_RS +  96 + lane];
            u64 ws[4];
            PACK2(ws[0], w0, w0); PACK2(ws[1], w1, w1);
            PACK2(ws[2], w2, w2); PACK2(ws[3], w3, w3);
            #pragma unroll
            for (int tp = 0; tp < 8; tp++) {
                FMA2(acc[tp][0], xq[tp], ws[0], acc[tp][0]);
                FMA2(acc[tp][1], xq[tp], ws[1], acc[tp][1]);
                FMA2(acc[tp][2], xq[tp], ws[2], acc[tp][2]);
                FMA2(acc[tp][3], xq[tp], ws[3], acc[tp][3]);
            }
        }
        __syncthreads();
    }

    // epilogue: acc[tp][0,1] = k cols (lane, 32+lane) -> dup pairs to g_kd
    //           acc[tp][2,3] = v cols (64+lane, 96+lane) -> g_kv
    #pragma unroll
    for (int tp = 0; tp < 8; tp++) {
        const size_t t = (size_t)tbase + w * 16 + tp * 2;
        float lo, hi;
        u64 dup;
        // k col lane
        UNPACK2(lo, hi, acc[tp][0]);
        PACK2(dup, lo, lo); g_kd[t * 64 + lane] = dup;
        PACK2(dup, hi, hi); g_kd[(t + 1) * 64 + lane] = dup;
        // k col 32+lane
        UNPACK2(lo, hi, acc[tp][1]);
        PACK2(dup, lo, lo); g_kd[t * 64 + 32 + lane] = dup;
        PACK2(dup, hi, hi); g_kd[(t + 1) * 64 + 32 + lane] = dup;
        // v cols
        UNPACK2(lo, hi, acc[tp][2]);
        g_kv[t * 128       + 64 + lane] = lo;
        g_kv[(t + 1) * 128 + 64 + lane] = hi;
        UNPACK2(lo, hi, acc[tp][3]);
        g_kv[t * 128       + 96 + lane] = lo;
        g_kv[(t + 1) * 128 + 96 + lane] = hi;
    }
}

// ---------------------------------------------------------------------------
// K2: attn + argmax + one-hot + v scatter.  2048 blocks x 256 thr, 64 tokens.
// Inner loop is now mov-free: k comes pre-duplicated from g_kd via one
// broadcast LDS.64 per (t, j), feeding FMA2 directly.
// smem: q2p [64 j][129 u64], ksd [64 tok][65 u64].
// ---------------------------------------------------------------------------
#define QRS 129                       // u64 row stride
#define KSD_RS 65                     // u64 row stride for dup-k
#define SMEM_ATTN ((64 * QRS + 64 * KSD_RS) * 8)

__global__ void __launch_bounds__(256, 2) k_attn(
    float* __restrict__ hard)
{
    extern __shared__ char smraw[];
    u64* q2p = (u64*)smraw;                    // [64][129]
    u64* ksd = q2p + 64 * QRS;                 // [64][65]

    const int tid  = threadIdx.x;
    const int lane = tid & 31;
    const int w    = tid >> 5;
    const int tblk = blockIdx.x * 64;

    // fill q2p: linear float4 copy of packed image (L2-resident)
    {
        const float4* qsrc = (const float4*)g_qp;
        float4* qdst = (float4*)q2p;
        #pragma unroll
        for (int it = 0; it < 17; it++) {
            const int i = it * 256 + tid;
            if (i < 4128) qdst[i] = qsrc[i];
        }
    }
    // fill ksd: linear copy of dup-k rows (coalesced LDG.64, STS 2-phase)
    #pragma unroll
    for (int it = 0; it < 16; it++) {
        const int i = it * 256 + tid;
        const int row = i >> 6, col = i & 63;
        ksd[row * KSD_RS + col] = g_kd[(size_t)(tblk + row) * 64 + col];
    }
    __syncthreads();

    u64 A[8][4];
    #pragma unroll
    for (int t = 0; t < 8; t++)
        #pragma unroll
        for (int i = 0; i < 4; i++) A[t][i] = 0ull;

    for (int j = 0; j < 64; j += 2) {
        u64 qv0[4], qv1[4];
        #pragma unroll
        for (int i = 0; i < 4; i++) {
            qv0[i] = q2p[j * QRS + i * 32 + lane];
            qv1[i] = q2p[(j + 1) * QRS + i * 32 + lane];
        }
        #pragma unroll
        for (int t = 0; t < 8; t++) {
            const u64 kaa = ksd[(w * 8 + t) * KSD_RS + j];      // bcast LDS.64
            const u64 kbb = ksd[(w * 8 + t) * KSD_RS + j + 1];  // bcast LDS.64
            FMA2(A[t][0], kaa, qv0[0], A[t][0]);
            FMA2(A[t][1], kaa, qv0[1], A[t][1]);
            FMA2(A[t][2], kaa, qv0[2], A[t][2]);
            FMA2(A[t][3], kaa, qv0[3], A[t][3]);
            FMA2(A[t][0], kbb, qv1[0], A[t][0]);
            FMA2(A[t][1], kbb, qv1[1], A[t][1]);
            FMA2(A[t][2], kbb, qv1[2], A[t][2]);
            FMA2(A[t][3], kbb, qv1[3], A[t][3]);
        }
    }

    // epilogue
    #pragma unroll
    for (int t = 0; t < 8; t++) {
        const int tglob = tblk + w * 8 + t;
        float lo[4], hi[4];
        #pragma unroll
        for (int i = 0; i < 4; i++) UNPACK2(lo[i], hi[i], A[t][i]);

        float bv = lo[0]; int bi = lane;
        #pragma unroll
        for (int i = 1; i < 4; i++)
            if (lo[i] > bv) { bv = lo[i]; bi = i * 32 + lane; }
        #pragma unroll
        for (int i = 0; i < 4; i++)
            if (hi[i] > bv) { bv = hi[i]; bi = 128 + i * 32 + lane; }
        #pragma unroll
        for (int off = 16; off > 0; off >>= 1) {
            const float ov = __shfl_xor_sync(0xffffffffu, bv, off);
            const int   oi = __shfl_xor_sync(0xffffffffu, bi, off);
            if (ov > bv || (ov == bv && oi < bi)) { bv = ov; bi = oi; }
        }

        // one-hot row
        float4* hp = (float4*)(hard + (size_t)tglob * 256);
        const int c0 = lane * 8;
        float4 o0, o1;
        o0.x = (c0 + 0 == bi) ? 1.f : 0.f;  o0.y = (c0 + 1 == bi) ? 1.f : 0.f;
        o0.z = (c0 + 2 == bi) ? 1.f : 0.f;  o0.w = (c0 + 3 == bi) ? 1.f : 0.f;
        o1.x = (c0 + 4 == bi) ? 1.f : 0.f;  o1.y = (c0 + 5 == bi) ? 1.f : 0.f;
        o1.z = (c0 + 6 == bi) ? 1.f : 0.f;  o1.w = (c0 + 7 == bi) ? 1.f : 0.f;
        hp[lane * 2]     = o0;
        hp[lane * 2 + 1] = o1;

        // scatter v
        const float* vp = g_kv + (size_t)tglob * 128 + 64;
        const float v0 = vp[lane], v1 = vp[32 + lane];
        const int b = tglob >> 13;
        float* pp = g_pooled + (size_t)(b * 256 + bi) * 64;
        atomicAdd(pp + lane,      v0);
        atomicAdd(pp + 32 + lane, v1);
    }
}

// ---------------------------------------------------------------------------
// K3: out[b,q,d] = sum_v pooled[b,q,v] * w_fc[d,v]
// 128 blocks x 256 thr, 32 rows/block. Weights read straight from gmem into
// 16 float4 regs (L2-resident); only the 8KB pooled slice staged in smem.
// ---------------------------------------------------------------------------
__global__ void __launch_bounds__(256, 2) k_fc(
    const float* __restrict__ wfc,
    float* __restrict__ out)
{
    __shared__ float s_p[32 * 64];     // 8 KB

    const int tid = threadIdx.x;
    const int r0 = blockIdx.x * 32;

    // stage pooled rows (512 float4, coalesced)
    {
        const float4* psrc = (const float4*)(g_pooled + (size_t)r0 * 64);
        float4* pdst = (float4*)s_p;
        #pragma unroll
        for (int it = 0; it < 2; it++)
            pdst[it * 256 + tid] = psrc[it * 256 + tid];
    }
    __syncthreads();

    const int d = tid;
    float4 W[16];
    #pragma unroll
    for (int m = 0; m < 16; m++)
        W[m] = *(const float4*)&wfc[d * 64 + m * 4];

    #pragma unroll
    for (int half = 0; half < 2; half++) {
        float acc[16];
        #pragma unroll
        for (int r = 0; r < 16; r++) acc[r] = 0.f;

        #pragma unroll
        for (int m = 0; m < 16; m++) {
            #pragma unroll
            for (int r = 0; r < 16; r++) {
                const float4 p = *(const float4*)&s_p[(half * 16 + r) * 64 + m * 4];
                acc[r] = fmaf(p.x, W[m].x, acc[r]);
                acc[r] = fmaf(p.y, W[m].y, acc[r]);
                acc[r] = fmaf(p.z, W[m].z, acc[r]);
                acc[r] = fmaf(p.w, W[m].w, acc[r]);
            }
        }
        #pragma unroll
        for (int r = 0; r < 16; r++)
            out[(size_t)(r0 + half * 16 + r) * 256 + d] = acc[r];
    }
}

// ---------------------------------------------------------------------------
extern "C" void kernel_launch(void* const* d_in, const int* in_sizes, int n_in,
                              void* d_out, int out_size)
{
    const float* x   = (const float*)d_in[0];
    const float* q   = (const float*)d_in[1];
    const float* wks = (const float*)d_in[2];
    const float* wvs = (const float*)d_in[3];
    const float* wfc = (const float*)d_in[4];

    float* out  = (float*)d_out;
    float* hard = out + OUT_ELE;

    static bool attr_done = false;
    if (!attr_done) {
        cudaFuncSetAttribute(k_proj, cudaFuncAttributeMaxDynamicSharedMemorySize, SMEM_PROJ);
        cudaFuncSetAttribute(k_attn, cudaFuncAttributeMaxDynamicSharedMemorySize, SMEM_ATTN);
        attr_done = true;
    }

    k_pack<<<129, 256>>>(q, wks, wvs);
    k_proj<<<1024, 256, SMEM_PROJ>>>(x);
    k_attn<<<2048, 256, SMEM_ATTN>>>(hard);
    k_fc<<<128, 256>>>(wfc, out);
}

// round 14
// speedup vs baseline: 1.0326x; 1.0326x over previous
#include <cuda_runtime.h>
#include <cstdint>

#define OUT_ELE (16 * 256 * 256)

typedef unsigned long long u64;

#define PACK2(d, lo, hi) \
    asm("mov.b64 %0, {%1, %2};" : "=l"(d) : "r"(__float_as_uint(lo)), "r"(__float_as_uint(hi)))
#define UNPACK2(lo, hi, s) do { unsigned _ulo, _uhi; \
    asm("mov.b64 {%0, %1}, %2;" : "=r"(_ulo), "=r"(_uhi) : "l"(s)); \
    lo = __uint_as_float(_ulo); hi = __uint_as_float(_uhi); } while (0)
#define FMA2(d, a, b, c) \
    asm("fma.rn.f32x2 %0, %1, %2, %3;" : "=l"(d) : "l"(a), "l"(b), "l"(c))

// scratch
__device__ float g_pooled[16 * 256 * 64];           // 1 MB
__device__ float g_kv[131072 * 128];                // 64 MB: cols 0-63 = k, 64-127 = v
__device__ float g_wt[4 * 64 * 129];                // per-chunk weight smem images
__device__ u64   g_qp[64 * 129];                    // packed-q smem image

// ---------------------------------------------------------------------------
// K0: pack weights + q into exact smem-image layouts (one launch, ~4us).
// ---------------------------------------------------------------------------
__global__ void __launch_bounds__(256) k_pack(
    const float* __restrict__ q,
    const float* __restrict__ wks,
    const float* __restrict__ wvs)
{
    const int i = blockIdx.x * 256 + threadIdx.x;
    if (i < 4 * 64 * 129) {
        const int chunk = i / 8256, rem = i % 8256, d = rem / 129, c = rem % 129;
        float val = 0.f;
        if (c < 128)
            val = (c < 64) ? wks[c * 256 + chunk * 64 + d]
                           : wvs[(c - 64) * 256 + chunk * 64 + d];
        g_wt[i] = val;
    }
    if (i < 64 * 129) {
        const int j = i / 129, rr = i % 129;
        u64 val = 0ull;
        if (rr < 128) PACK2(val, q[rr * 64 + j], q[(rr + 128) * 64 + j]);
        g_qp[i] = val;
    }
}

// ---------------------------------------------------------------------------
// K1: kv projection GEMM (+ pooled zeroing folded into first 256 blocks).
// == R12 version (known good): k -> g_kv cols 0-63, v -> cols 64-127 ==
// ---------------------------------------------------------------------------
#define SP_F  (64 * 130)
#define SW_RS 129
#define SMEM_PROJ ((SP_F + 64 * SW_RS) * 4)

__global__ void __launch_bounds__(256, 2) k_proj(
    const float* __restrict__ x)
{
    extern __shared__ float sm[];
    float* sp_f = sm;                 // [64][130] f32 == [64][65] u64
    u64*   sp64 = (u64*)sp_f;
    float* sw   = sm + SP_F;          // [64][129]  (16B-aligned)

    const int tid  = threadIdx.x;
    const int lane = tid & 31;
    const int w    = tid >> 5;
    const int tbase = blockIdx.x * 128;

    // folded pooled zeroing
    if (blockIdx.x < 256) {
        reinterpret_cast<float4*>(g_pooled)[blockIdx.x * 256 + tid] =
            make_float4(0.f, 0.f, 0.f, 0.f);
    }

    u64 acc[8][4];
    #pragma unroll
    for (int tp = 0; tp < 8; tp++)
        #pragma unroll
        for (int c = 0; c < 4; c++) acc[tp][c] = 0ull;

    for (int chunk = 0; chunk < 4; chunk++) {
        const int d0 = chunk * 64;

        // fill sw: linear float4 copy of the image (coalesced, conflict-free)
        {
            const float4* wsrc = (const float4*)(g_wt + chunk * 8256);
            float4* wdst = (float4*)sw;
            #pragma unroll
            for (int it = 0; it < 9; it++) {
                const int i = it * 256 + tid;
                if (i < 2064) wdst[i] = wsrc[i];
            }
        }
        // fill sp: pair-packed x (STS 2-way max)
        #pragma unroll
        for (int rr = 0; rr < 16; rr++) {
            const int tl = w * 16 + rr;
            const float* xp = x + (size_t)(tbase + tl) * 256 + d0;
            const int g = tl >> 1, h = tl & 1;
            sp_f[lane * 130 + g * 2 + h]        = xp[lane];
            sp_f[(32 + lane) * 130 + g * 2 + h] = xp[32 + lane];
        }
        __syncthreads();

        #pragma unroll 2
        for (int d = 0; d < 64; d++) {
            u64 xq[8];
            #pragma unroll
            for (int tp = 0; tp < 8; tp++)
                xq[tp] = sp64[d * 65 + w * 8 + tp];          // broadcast LDS.64
            const float w0 = sw[d * SW_RS +       lane];
            const float w1 = sw[d * SW_RS +  32 + lane];
            const float w2 = sw[d * SW_RS +  64 + lane];
            const float w3 = sw[d * SW_RS +  96 + lane];
            u64 ws[4];
            PACK2(ws[0], w0, w0); PACK2(ws[1], w1, w1);
            PACK2(ws[2], w2, w2); PACK2(ws[3], w3, w3);
            #pragma unroll
            for (int tp = 0; tp < 8; tp++) {
                FMA2(acc[tp][0], xq[tp], ws[0], acc[tp][0]);
                FMA2(acc[tp][1], xq[tp], ws[1], acc[tp][1]);
                FMA2(acc[tp][2], xq[tp], ws[2], acc[tp][2]);
                FMA2(acc[tp][3], xq[tp], ws[3], acc[tp][3]);
            }
        }
        __syncthreads();
    }

    // epilogue: token (w*16 + 2tp [+1]), col lane + 32k  (coalesced STG.32)
    #pragma unroll
    for (int tp = 0; tp < 8; tp++) {
        const size_t t = (size_t)tbase + w * 16 + tp * 2;
        #pragma unroll
        for (int k = 0; k < 4; k++) {
            float lo, hi;
            UNPACK2(lo, hi, acc[tp][k]);
            g_kv[t * 128       + k * 32 + lane] = lo;
            g_kv[(t + 1) * 128 + k * 32 + lane] = hi;
        }
    }
}

// ---------------------------------------------------------------------------
// K2: attn + argmax + one-hot + v scatter.  2048 blocks x 256 thr, 64 tokens.
// Mov-free inner loop: k duplicated-pair image built IN SMEM during the fill
// (from g_kv - no extra HBM traffic), consumed via broadcast LDS.64 -> FMA2.
// smem: q2p [64 j][129 u64], ksd [64 tok][65 u64].
// ---------------------------------------------------------------------------
#define QRS 129                       // u64 row stride
#define KSD_RS 65                     // u64 row stride for dup-k
#define SMEM_ATTN ((64 * QRS + 64 * KSD_RS) * 8)

__global__ void __launch_bounds__(256, 2) k_attn(
    float* __restrict__ hard)
{
    extern __shared__ char smraw[];
    u64* q2p = (u64*)smraw;                    // [64][129]
    u64* ksd = q2p + 64 * QRS;                 // [64][65]

    const int tid  = threadIdx.x;
    const int lane = tid & 31;
    const int w    = tid >> 5;
    const int tblk = blockIdx.x * 64;

    // fill q2p: linear float4 copy of packed image (L2-resident)
    {
        const float4* qsrc = (const float4*)g_qp;
        float4* qdst = (float4*)q2p;
        #pragma unroll
        for (int it = 0; it < 17; it++) {
            const int i = it * 256 + tid;
            if (i < 4128) qdst[i] = qsrc[i];
        }
    }
    // fill ksd: dup-pack k in smem (coalesced LDG.32, STS.64 2-phase)
    #pragma unroll
    for (int it = 0; it < 16; it++) {
        const int i = it * 256 + tid;
        const int row = i >> 6, col = i & 63;
        const float kv = g_kv[(size_t)(tblk + row) * 128 + col];
        u64 dup; PACK2(dup, kv, kv);
        ksd[row * KSD_RS + col] = dup;
    }
    __syncthreads();

    u64 A[8][4];
    #pragma unroll
    for (int t = 0; t < 8; t++)
        #pragma unroll
        for (int i = 0; i < 4; i++) A[t][i] = 0ull;

    for (int j = 0; j < 64; j += 2) {
        u64 qv0[4], qv1[4];
        #pragma unroll
        for (int i = 0; i < 4; i++) {
            qv0[i] = q2p[j * QRS + i * 32 + lane];
            qv1[i] = q2p[(j + 1) * QRS + i * 32 + lane];
        }
        #pragma unroll
        for (int t = 0; t < 8; t++) {
            const u64 kaa = ksd[(w * 8 + t) * KSD_RS + j];      // bcast LDS.64
            const u64 kbb = ksd[(w * 8 + t) * KSD_RS + j + 1];  // bcast LDS.64
            FMA2(A[t][0], kaa, qv0[0], A[t][0]);
            FMA2(A[t][1], kaa, qv0[1], A[t][1]);
            FMA2(A[t][2], kaa, qv0[2], A[t][2]);
            FMA2(A[t][3], kaa, qv0[3], A[t][3]);
            FMA2(A[t][0], kbb, qv1[0], A[t][0]);
            FMA2(A[t][1], kbb, qv1[1], A[t][1]);
            FMA2(A[t][2], kbb, qv1[2], A[t][2]);
            FMA2(A[t][3], kbb, qv1[3], A[t][3]);
        }
    }

    // epilogue
    #pragma unroll
    for (int t = 0; t < 8; t++) {
        const int tglob = tblk + w * 8 + t;
        float lo[4], hi[4];
        #pragma unroll
        for (int i = 0; i < 4; i++) UNPACK2(lo[i], hi[i], A[t][i]);

        float bv = lo[0]; int bi = lane;
        #pragma unroll
        for (int i = 1; i < 4; i++)
            if (lo[i] > bv) { bv = lo[i]; bi = i * 32 + lane; }
        #pragma unroll
        for (int i = 0; i < 4; i++)
            if (hi[i] > bv) { bv = hi[i]; bi = 128 + i * 32 + lane; }
        #pragma unroll
        for (int off = 16; off > 0; off >>= 1) {
            const float ov = __shfl_xor_sync(0xffffffffu, bv, off);
            const int   oi = __shfl_xor_sync(0xffffffffu, bi, off);
            if (ov > bv || (ov == bv && oi < bi)) { bv = ov; bi = oi; }
        }

        // one-hot row
        float4* hp = (float4*)(hard + (size_t)tglob * 256);
        const int c0 = lane * 8;
        float4 o0, o1;
        o0.x = (c0 + 0 == bi) ? 1.f : 0.f;  o0.y = (c0 + 1 == bi) ? 1.f : 0.f;
        o0.z = (c0 + 2 == bi) ? 1.f : 0.f;  o0.w = (c0 + 3 == bi) ? 1.f : 0.f;
        o1.x = (c0 + 4 == bi) ? 1.f : 0.f;  o1.y = (c0 + 5 == bi) ? 1.f : 0.f;
        o1.z = (c0 + 6 == bi) ? 1.f : 0.f;  o1.w = (c0 + 7 == bi) ? 1.f : 0.f;
        hp[lane * 2]     = o0;
        hp[lane * 2 + 1] = o1;

        // scatter v
        const float* vp = g_kv + (size_t)tglob * 128 + 64;
        const float v0 = vp[lane], v1 = vp[32 + lane];
        const int b = tglob >> 13;
        float* pp = g_pooled + (size_t)(b * 256 + bi) * 64;
        atomicAdd(pp + lane,      v0);
        atomicAdd(pp + 32 + lane, v1);
    }
}

// ---------------------------------------------------------------------------
// K3: out[b,q,d] = sum_v pooled[b,q,v] * w_fc[d,v]
// == R13 version (measured 11.6us): 128 blocks x 32 rows, weights in regs ==
// ---------------------------------------------------------------------------
__global__ void __launch_bounds__(256, 2) k_fc(
    const float* __restrict__ wfc,
    float* __restrict__ out)
{
    __shared__ float s_p[32 * 64];     // 8 KB

    const int tid = threadIdx.x;
    const int r0 = blockIdx.x * 32;

    // stage pooled rows (512 float4, coalesced)
    {
        const float4* psrc = (const float4*)(g_pooled + (size_t)r0 * 64);
        float4* pdst = (float4*)s_p;
        #pragma unroll
        for (int it = 0; it < 2; it++)
            pdst[it * 256 + tid] = psrc[it * 256 + tid];
    }
    __syncthreads();

    const int d = tid;
    float4 W[16];
    #pragma unroll
    for (int m = 0; m < 16; m++)
        W[m] = *(const float4*)&wfc[d * 64 + m * 4];

    #pragma unroll
    for (int half = 0; half < 2; half++) {
        float acc[16];
        #pragma unroll
        for (int r = 0; r < 16; r++) acc[r] = 0.f;

        #pragma unroll
        for (int m = 0; m < 16; m++) {
            #pragma unroll
            for (int r = 0; r < 16; r++) {
                const float4 p = *(const float4*)&s_p[(half * 16 + r) * 64 + m * 4];
                acc[r] = fmaf(p.x, W[m].x, acc[r]);
                acc[r] = fmaf(p.y, W[m].y, acc[r]);
                acc[r] = fmaf(p.z, W[m].z, acc[r]);
                acc[r] = fmaf(p.w, W[m].w, acc[r]);
            }
        }
        #pragma unroll
        for (int r = 0; r < 16; r++)
            out[(size_t)(r0 + half * 16 + r) * 256 + d] = acc[r];
    }
}

// ---------------------------------------------------------------------------
extern "C" void kernel_launch(void* const* d_in, const int* in_sizes, int n_in,
                              void* d_out, int out_size)
{
    const float* x   = (const float*)d_in[0];
    const float* q   = (const float*)d_in[1];
    const float* wks = (const float*)d_in[2];
    const float* wvs = (const float*)d_in[3];
    const float* wfc = (const float*)d_in[4];

    float* out  = (float*)d_out;
    float* hard = out + OUT_ELE;

    static bool attr_done = false;
    if (!attr_done) {
        cudaFuncSetAttribute(k_proj, cudaFuncAttributeMaxDynamicSharedMemorySize, SMEM_PROJ);
        cudaFuncSetAttribute(k_attn, cudaFuncAttributeMaxDynamicSharedMemorySize, SMEM_ATTN);
        attr_done = true;
    }

    k_pack<<<129, 256>>>(q, wks, wvs);
    k_proj<<<1024, 256, SMEM_PROJ>>>(x);
    k_attn<<<2048, 256, SMEM_ATTN>>>(hard);
    k_fc<<<128, 256>>>(wfc, out);
}